// round 1
// baseline (speedup 1.0000x reference)
#include <cuda_runtime.h>
#include <cuda_bf16.h>

// SpMM: out[r] = sum over edges (r,c,v) of v * x[c], rows sorted (CSR order).
// N_NODES = 100000, N_EDGES = 1600000, D = 48.

#define D_FEAT 48
#define TPR 16          // threads per row (each owns 3 feature cols)
#define RPB 16          // rows per block  -> 256 threads/block
#define MAX_NODES 100000

// Scratch: CSR row pointers (no cudaMalloc allowed; __device__ global is the
// sanctioned workaround).
__device__ int g_row_ptr[MAX_NODES + 1];

// Kernel 1: build row_ptr by binary search (rows is sorted).
// row_ptr[r] = lower_bound(rows, r); row_ptr[N] = E.
__global__ void build_row_ptr_kernel(const int* __restrict__ rows, int E, int N) {
    int r = blockIdx.x * blockDim.x + threadIdx.x;
    if (r > N) return;
    if (r == N) { g_row_ptr[N] = E; return; }
    int lo = 0, hi = E;
    while (lo < hi) {
        int mid = (lo + hi) >> 1;
        if (__ldg(&rows[mid]) < r) lo = mid + 1;
        else hi = mid;
    }
    g_row_ptr[r] = lo;
}

// Kernel 2: CSR SpMM, no atomics. blockDim = (TPR, RPB).
// Thread (tx, ty) accumulates cols {tx, tx+16, tx+32} of row
// blockIdx.x*RPB + ty in registers, writes once.
__global__ void __launch_bounds__(TPR * RPB)
spmm_csr_kernel(const float* __restrict__ x,
                const int* __restrict__ cols,
                const float* __restrict__ vals,
                float* __restrict__ out,
                int N) {
    int row = blockIdx.x * RPB + threadIdx.y;
    if (row >= N) return;
    const int tx = threadIdx.x;

    int e   = g_row_ptr[row];
    int end = g_row_ptr[row + 1];

    float a0 = 0.f, a1 = 0.f, a2 = 0.f;

    // Unroll-by-2 to expose more memory-level parallelism to the LSU.
    for (; e + 1 < end; e += 2) {
        int   c0 = __ldg(&cols[e]);
        int   c1 = __ldg(&cols[e + 1]);
        float v0 = __ldg(&vals[e]);
        float v1 = __ldg(&vals[e + 1]);
        const float* xr0 = x + (size_t)c0 * D_FEAT;
        const float* xr1 = x + (size_t)c1 * D_FEAT;
        float b00 = xr0[tx], b01 = xr0[tx + 16], b02 = xr0[tx + 32];
        float b10 = xr1[tx], b11 = xr1[tx + 16], b12 = xr1[tx + 32];
        a0 += v0 * b00; a1 += v0 * b01; a2 += v0 * b02;
        a0 += v1 * b10; a1 += v1 * b11; a2 += v1 * b12;
    }
    if (e < end) {
        int   c = __ldg(&cols[e]);
        float v = __ldg(&vals[e]);
        const float* xr = x + (size_t)c * D_FEAT;
        a0 += v * xr[tx]; a1 += v * xr[tx + 16]; a2 += v * xr[tx + 32];
    }

    float* o = out + (size_t)row * D_FEAT;
    o[tx]      = a0;
    o[tx + 16] = a1;
    o[tx + 32] = a2;
}

extern "C" void kernel_launch(void* const* d_in, const int* in_sizes, int n_in,
                              void* d_out, int out_size) {
    // metadata order: t, x, rows, cols, vals
    const float* x    = (const float*)d_in[1];
    const int*   rows = (const int*)d_in[2];
    const int*   cols = (const int*)d_in[3];
    const float* vals = (const float*)d_in[4];
    float*       out  = (float*)d_out;

    const int E = in_sizes[2];
    const int N = out_size / D_FEAT;

    {
        int threads = 256;
        int blocks  = (N + 1 + threads - 1) / threads;
        build_row_ptr_kernel<<<blocks, threads>>>(rows, E, N);
    }
    {
        dim3 block(TPR, RPB);
        int  grid = (N + RPB - 1) / RPB;
        spmm_csr_kernel<<<grid, block>>>(x, cols, vals, out, N);
    }
}